// round 13
// baseline (speedup 1.0000x reference)
#include <cuda_runtime.h>

#define IMG_H 512
#define IMG_W 512
#define OUT_H 502
#define OUT_W 502
#define NIMG 32
#define HALO 10
#define STRIP 28          // output rows per block (18 strips: 17x28 + 26)
#define NSTRIPS 18
#define NTHREADS 256
#define NBLOCKS (NSTRIPS * NIMG)   // 576 = 97.3% of 2 full waves at occ 2
#define NCP 266           // column-pairs per smem row (264 used + pad)

__device__ float g_partial[NBLOCKS * 2];
__device__ unsigned g_count = 0;

// ---- packed f32x2 helpers (ptxas never fuses these from C++) ----
typedef unsigned long long u64t;
__device__ __forceinline__ u64t pk2(float lo, float hi) {
    u64t r; asm("mov.b64 %0, {%1,%2};" : "=l"(r) : "f"(lo), "f"(hi)); return r;
}
__device__ __forceinline__ void upk2(u64t v, float& lo, float& hi) {
    asm("mov.b64 {%0,%1}, %2;" : "=f"(lo), "=f"(hi) : "l"(v));
}
__device__ __forceinline__ u64t fma2(u64t a, u64t b, u64t c) {
    u64t d; asm("fma.rn.f32x2 %0, %1, %2, %3;" : "=l"(d) : "l"(a), "l"(b), "l"(c)); return d;
}
__device__ __forceinline__ u64t mul2(u64t a, u64t b) {
    u64t d; asm("mul.rn.f32x2 %0, %1, %2;" : "=l"(d) : "l"(a), "l"(b)); return d;
}
__device__ __forceinline__ u64t add2(u64t a, u64t b) {
    u64t d; asm("add.rn.f32x2 %0, %1, %2;" : "=l"(d) : "l"(a), "l"(b)); return d;
}

// Horizontal 11-tap blur, symmetric-folded (GW[k]==GW[10-k]): per channel
// 5 add2 + 1 mul2 + 5 fma2 using only GWS[0..5]. Both channel-pairs of one
// float4 row; even-k packs are adjacent register pairs (fold free).
__device__ __forceinline__ void hblur2(const float4* __restrict__ q,
                                       const u64t* __restrict__ GWS,
                                       u64t& hA, u64t& hB)
{
    // tap k (packed 2 outputs): even k -> (q[k/2].x,.y)/(.z,.w); odd -> crossing
#define TA(k) (((k) & 1) ? pk2(q[(k) >> 1].y, q[((k) >> 1) + 1].x) \
                         : pk2(q[(k) >> 1].x, q[(k) >> 1].y))
#define TB(k) (((k) & 1) ? pk2(q[(k) >> 1].w, q[((k) >> 1) + 1].z) \
                         : pk2(q[(k) >> 1].z, q[(k) >> 1].w))
    hA = mul2(GWS[0], add2(TA(0), TA(10)));
    hB = mul2(GWS[0], add2(TB(0), TB(10)));
#pragma unroll
    for (int k = 1; k < 5; ++k) {
        hA = fma2(GWS[k], add2(TA(k), TA(10 - k)), hA);
        hB = fma2(GWS[k], add2(TB(k), TB(10 - k)), hB);
    }
    hA = fma2(GWS[5], TA(5), hA);
    hB = fma2(GWS[5], TB(5), hB);
#undef TA
#undef TB
}

__global__ __launch_bounds__(NTHREADS, 2)
void fused_mse_ssim(const float* __restrict__ pred, const float* __restrict__ targ,
                    float* __restrict__ out)
{
    const float GW[6] = {   // symmetric half of the normalized 11-tap gaussian
        0.00102838f, 0.00759876f, 0.03600077f, 0.10936070f, 0.21300554f,
        0.26601172f
    };
    u64t GWS[6];
#pragma unroll
    for (int k = 0; k < 6; ++k) GWS[k] = pk2(GW[k], GW[k]);
    const float C1 = 1e-4f, C2 = 9e-4f;

    // Smem holds VERTICALLY-BLURRED completed rows only (2 rows/phase, dbl buf).
    __shared__ float4 sAB[2][2][NCP];   // (VP0, VP1, VT0, VT1)
    __shared__ float4 sCD[2][2][NCP];   // (VSS0, VSS1, VDD0, VDD1)
    __shared__ float red_m[8], red_s[8];
    __shared__ unsigned s_ticket;

    const int tid = threadIdx.x;
    const int y0  = blockIdx.x * STRIP;
    const int img = blockIdx.y;

    const int n_in     = min(STRIP, OUT_H - y0) + HALO;   // 38 or 36 (even)
    const int mse_rows = min(IMG_H - y0, (blockIdx.x == NSTRIPS - 1) ? 999 : STRIP);

    const float* __restrict__ pbase = pred + (size_t)img * (IMG_H * IMG_W);
    const float* __restrict__ tbase = targ + (size_t)img * (IMG_H * IMG_W);

    // Ring of RAW channel values (col-pair packed): 11 rows x 4 channels.
    u64t rgP[11], rgT[11], rgSS[11], rgDD[11];
#pragma unroll
    for (int j = 0; j < 11; ++j) { rgP[j] = rgT[j] = rgSS[j] = rgDD[j] = 0ull; }

    u64t mse2 = 0ull;
    float ssim_acc = 0.f;
    const bool emit_col = (tid <= 250);

    // Preload rows 0 and 1
    float2 pp0 = ((const float2*)(pbase + (size_t)(y0 + 0) * IMG_W))[tid];
    float2 tt0 = ((const float2*)(tbase + (size_t)(y0 + 0) * IMG_W))[tid];
    float2 pp1 = ((const float2*)(pbase + (size_t)(y0 + 1) * IMG_W))[tid];
    float2 tt1 = ((const float2*)(tbase + (size_t)(y0 + 1) * IMG_W))[tid];

    // Symmetric-folded vertical gather for output row whose taps occupy ring
    // slots (jb+1+i)%11, i=0..10. Stores result straight to smem (kills vb
    // liveness before the next insert).
#define VGATHER_STORE(jb, dstAB, dstCD)                                        \
    {                                                                          \
        u64t v0, v1, v2, v3;                                                   \
        {                                                                      \
            const int a = ((jb) + 1) % 11, b = ((jb) + 11) % 11;               \
            v0 = mul2(GWS[0], add2(rgP[a],  rgP[b]));                          \
            v1 = mul2(GWS[0], add2(rgT[a],  rgT[b]));                          \
            v2 = mul2(GWS[0], add2(rgSS[a], rgSS[b]));                         \
            v3 = mul2(GWS[0], add2(rgDD[a], rgDD[b]));                         \
        }                                                                      \
        _Pragma("unroll")                                                      \
        for (int i = 1; i < 5; ++i) {                                          \
            const int a = ((jb) + 1 + i) % 11, b = ((jb) + 11 - i) % 11;       \
            v0 = fma2(GWS[i], add2(rgP[a],  rgP[b]),  v0);                     \
            v1 = fma2(GWS[i], add2(rgT[a],  rgT[b]),  v1);                     \
            v2 = fma2(GWS[i], add2(rgSS[a], rgSS[b]), v2);                     \
            v3 = fma2(GWS[i], add2(rgDD[a], rgDD[b]), v3);                     \
        }                                                                      \
        {                                                                      \
            const int c = ((jb) + 6) % 11;                                     \
            v0 = fma2(GWS[5], rgP[c],  v0);                                    \
            v1 = fma2(GWS[5], rgT[c],  v1);                                    \
            v2 = fma2(GWS[5], rgSS[c], v2);                                    \
            v3 = fma2(GWS[5], rgDD[c], v3);                                    \
        }                                                                      \
        float a0, a1, b0, b1;                                                  \
        upk2(v0, a0, a1); upk2(v1, b0, b1);                                    \
        (dstAB)[tid] = make_float4(a0, a1, b0, b1);                            \
        upk2(v2, a0, a1); upk2(v3, b0, b1);                                    \
        (dstCD)[tid] = make_float4(a0, a1, b0, b1);                            \
    }

    for (int rb = 0; rb < 44; rb += 22) {          // 22 ≡ 0 (mod 11)
#pragma unroll
        for (int pj = 0; pj < 11; ++pj) {
            const int r0 = rb + 2 * pj;            // even row of pair
            const int j0 = (2 * pj) % 11;          // static slot indices
            const int j1 = (2 * pj + 1) % 11;
            if (r0 < n_in) {                       // block-uniform
                const bool hasem = (r0 >= HALO);   // block-uniform
                const int par = ((r0 - HALO) >> 1) & 1;

                // ---- insert row r0 into ring ----
                {
                    float s0 = pp0.x + tt0.x, d0 = pp0.x - tt0.x;
                    float s1 = pp0.y + tt0.y, d1 = pp0.y - tt0.y;
                    rgP[j0]  = pk2(pp0.x, pp0.y);
                    rgT[j0]  = pk2(tt0.x, tt0.y);
                    rgSS[j0] = pk2(s0 * s0, s1 * s1);
                    u64t DD  = pk2(d0 * d0, d1 * d1);
                    rgDD[j0] = DD;
                    if (r0 < mse_rows) mse2 = add2(mse2, DD);
                }

                // ---- vgather o0 = r0-10, store immediately (before r1 insert
                //      evicts row r0-10 from the ring) ----
                if (hasem) VGATHER_STORE(j0, sAB[par][0], sCD[par][0]);

                // ---- insert row r1 ----
                {
                    float s0 = pp1.x + tt1.x, d0 = pp1.x - tt1.x;
                    float s1 = pp1.y + tt1.y, d1 = pp1.y - tt1.y;
                    rgP[j1]  = pk2(pp1.x, pp1.y);
                    rgT[j1]  = pk2(tt1.x, tt1.y);
                    rgSS[j1] = pk2(s0 * s0, s1 * s1);
                    u64t DD  = pk2(d0 * d0, d1 * d1);
                    rgDD[j1] = DD;
                    if (r0 + 1 < mse_rows) mse2 = add2(mse2, DD);
                }

                // ---- vgather o1 = r1-10, store ----
                if (hasem) VGATHER_STORE(j1, sAB[par][1], sCD[par][1]);

                // ---- prefetch next pair (hide LDG across hblur phase) ----
                if (r0 + 2 < n_in) {
                    const size_t off = (size_t)(y0 + r0 + 2) * IMG_W;
                    pp0 = ((const float2*)(pbase + off))[tid];
                    tt0 = ((const float2*)(tbase + off))[tid];
                    const size_t off1 = off + IMG_W;
                    pp1 = ((const float2*)(pbase + off1))[tid];
                    tt1 = ((const float2*)(tbase + off1))[tid];
                }

                if (hasem) {
                    __syncthreads();

                    // ---- horizontal blur + SSIM for both completed rows ----
#pragma unroll
                    for (int rr = 0; rr < 2; ++rr) {
                        float4 qAB[6], qCD[6];
#pragma unroll
                        for (int m = 0; m < 6; ++m) {   // batch all 12 LDS.128
                            qAB[m] = sAB[par][rr][tid + m];
                            qCD[m] = sCD[par][rr][tid + m];
                        }
                        u64t M1p, M2p, BSp, BDp;
                        hblur2(qAB, GWS, M1p, M2p);
                        hblur2(qCD, GWS, BSp, BDp);
                        if (emit_col) {
                            float M1[2], M2[2], BS[2], BD[2];
                            upk2(M1p, M1[0], M1[1]);
                            upk2(M2p, M2[0], M2[1]);
                            upk2(BSp, BS[0], BS[1]);
                            upk2(BDp, BD[0], BD[1]);
#pragma unroll
                            for (int col = 0; col < 2; ++col) {
                                float m1s = M1[col] * M1[col];
                                float m2s = M2[col] * M2[col];
                                float m12 = M1[col] * M2[col];
                                float sums = m1s + m2s;
                                float sigsum = fmaf(0.5f,  BS[col] + BD[col], -sums);
                                float sig12  = fmaf(0.25f, BS[col] - BD[col], -m12);
                                float num = (2.f * m12 + C1) * (2.f * sig12 + C2);
                                float den = fmaf(sums + C1, sigsum + C2, 1e-6f);
                                ssim_acc += __fdividef(num, den);
                            }
                        }
                    }
                }
            }
        }
    }
#undef VGATHER_STORE

    // Unpack packed MSE accumulator
    float mse_acc;
    { float mlo, mhi; upk2(mse2, mlo, mhi); mse_acc = mlo + mhi; }

    // Block reduction
#pragma unroll
    for (int off = 16; off > 0; off >>= 1) {
        mse_acc  += __shfl_down_sync(0xffffffffu, mse_acc,  off);
        ssim_acc += __shfl_down_sync(0xffffffffu, ssim_acc, off);
    }
    const int wrp = tid >> 5, lane = tid & 31;
    if (lane == 0) { red_m[wrp] = mse_acc; red_s[wrp] = ssim_acc; }
    __syncthreads();
    if (tid == 0) {
        float m = 0.f, s = 0.f;
#pragma unroll
        for (int w = 0; w < 8; ++w) { m += red_m[w]; s += red_s[w]; }
        const int bid = blockIdx.y * NSTRIPS + blockIdx.x;
        g_partial[bid * 2 + 0] = m;
        g_partial[bid * 2 + 1] = s;
        __threadfence();
        s_ticket = atomicAdd(&g_count, 1u);
    }
    __syncthreads();

    // Last block folds in the final reduction (no 2nd launch)
    if (s_ticket == NBLOCKS - 1) {
        __threadfence();
        double m = 0.0, s = 0.0;
        for (int i = tid; i < NBLOCKS; i += NTHREADS) {
            m += (double)g_partial[i * 2 + 0];
            s += (double)g_partial[i * 2 + 1];
        }
#pragma unroll
        for (int off = 16; off > 0; off >>= 1) {
            m += __shfl_down_sync(0xffffffffu, m, off);
            s += __shfl_down_sync(0xffffffffu, s, off);
        }
        __shared__ double sm[8], ss[8];
        if (lane == 0) { sm[wrp] = m; ss[wrp] = s; }
        __syncthreads();
        if (tid == 0) {
            double M = 0.0, S = 0.0;
#pragma unroll
            for (int w = 0; w < 8; ++w) { M += sm[w]; S += ss[w]; }
            const double mse_n  = (double)NIMG * IMG_H * IMG_W;
            const double ssim_n = (double)NIMG * OUT_H * OUT_W;
            double mse_loss  = M / mse_n;
            double ssim_loss = 1.0 - S / ssim_n;
            out[0] = (float)(0.6 * mse_loss + 0.4 * ssim_loss);
            g_count = 0;   // self-reset for next graph replay
        }
    }
}

extern "C" void kernel_launch(void* const* d_in, const int* in_sizes, int n_in,
                              void* d_out, int out_size)
{
    const float* pred = (const float*)d_in[0];
    const float* targ = (const float*)d_in[1];

    dim3 grid(NSTRIPS, NIMG, 1);   // 18 x 32 = 576 blocks
    fused_mse_ssim<<<grid, NTHREADS>>>(pred, targ, (float*)d_out);
}

// round 14
// speedup vs baseline: 1.0029x; 1.0029x over previous
#include <cuda_runtime.h>

#define IMG_H 512
#define IMG_W 512
#define OUT_H 502
#define OUT_W 502
#define NIMG 32
#define HALO 10
#define STRIP 28          // output rows per block (18 strips: 17x28 + 26)
#define NSTRIPS 18
#define NTHREADS 256
#define NBLOCKS (NSTRIPS * NIMG)   // 576 = 97.3% of 2 full waves at occ 2
#define NCP 266           // column-pairs per smem row (264 used + pad)

__device__ float g_partial[NBLOCKS * 2];
__device__ unsigned g_count = 0;

// ---- packed f32x2 helpers (ptxas never fuses these from C++) ----
typedef unsigned long long u64t;
__device__ __forceinline__ u64t pk2(float lo, float hi) {
    u64t r; asm("mov.b64 %0, {%1,%2};" : "=l"(r) : "f"(lo), "f"(hi)); return r;
}
__device__ __forceinline__ void upk2(u64t v, float& lo, float& hi) {
    asm("mov.b64 {%0,%1}, %2;" : "=f"(lo), "=f"(hi) : "l"(v));
}
__device__ __forceinline__ u64t fma2(u64t a, u64t b, u64t c) {
    u64t d; asm("fma.rn.f32x2 %0, %1, %2, %3;" : "=l"(d) : "l"(a), "l"(b), "l"(c)); return d;
}
__device__ __forceinline__ u64t mul2(u64t a, u64t b) {
    u64t d; asm("mul.rn.f32x2 %0, %1, %2;" : "=l"(d) : "l"(a), "l"(b)); return d;
}
__device__ __forceinline__ u64t add2(u64t a, u64t b) {
    u64t d; asm("add.rn.f32x2 %0, %1, %2;" : "=l"(d) : "l"(a), "l"(b)); return d;
}
__device__ __forceinline__ void named_bar(int id) {
    asm volatile("bar.sync %0, 64;" :: "r"(id) : "memory");
}

// Horizontal 11-tap blur for 2 adjacent output cols, TWO channels at once.
// Pair-interleave (A_even, A_odd, B_even, B_odd): even-k packs are adjacent
// register pairs from LDS.128 (fold free); only 5 odd-k packs/channel are real.
__device__ __forceinline__ void hblur2(const float4* __restrict__ row, int tid,
                                       const u64t* __restrict__ GWP,
                                       u64t& hA, u64t& hB)
{
    float4 q[6];
#pragma unroll
    for (int m = 0; m < 6; ++m) q[m] = row[tid + m];
    hA = mul2(GWP[0], pk2(q[0].x, q[0].y));
    hB = mul2(GWP[0], pk2(q[0].z, q[0].w));
#pragma unroll
    for (int k = 1; k < 11; ++k) {
        const int m = k >> 1;
        u64t PA = (k & 1) ? pk2(q[m].y, q[m + 1].x) : pk2(q[m].x, q[m].y);
        u64t PB = (k & 1) ? pk2(q[m].w, q[m + 1].z) : pk2(q[m].z, q[m].w);
        hA = fma2(GWP[k], PA, hA);
        hB = fma2(GWP[k], PB, hB);
    }
}

__global__ __launch_bounds__(NTHREADS, 2)
void fused_mse_ssim(const float* __restrict__ pred, const float* __restrict__ targ,
                    float* __restrict__ out)
{
    const float GW[11] = {
        0.00102838f, 0.00759876f, 0.03600077f, 0.10936070f, 0.21300554f,
        0.26601172f,
        0.21300554f, 0.10936070f, 0.03600077f, 0.00759876f, 0.00102838f
    };
    u64t GWP[11];
#pragma unroll
    for (int k = 0; k < 11; ++k) GWP[k] = pk2(GW[k], GW[k]);
    const float C1 = 1e-4f, C2 = 9e-4f;

    // Smem holds VERTICALLY-BLURRED completed rows only (2 rows/phase, dbl buf).
    __shared__ float4 sAB[2][2][NCP];   // (VP0, VP1, VT0, VT1)
    __shared__ float4 sCD[2][2][NCP];   // (VSS0, VSS1, VDD0, VDD1)
    __shared__ float red_m[8], red_s[8];
    __shared__ unsigned s_ticket;

    const int tid  = threadIdx.x;
    const int warp = tid >> 5;
    const int y0  = blockIdx.x * STRIP;
    const int img = blockIdx.y;

    const int n_in     = min(STRIP, OUT_H - y0) + HALO;   // 38 or 36 (even)
    const int mse_rows = min(IMG_H - y0, (blockIdx.x == NSTRIPS - 1) ? 999 : STRIP);

    const float* __restrict__ pbase = pred + (size_t)img * (IMG_H * IMG_W);
    const float* __restrict__ tbase = targ + (size_t)img * (IMG_H * IMG_W);

    // Ring of RAW channel values (col-pair packed): 11 rows x 4 channels.
    u64t rgP[11], rgT[11], rgSS[11], rgDD[11];
#pragma unroll
    for (int j = 0; j < 11; ++j) { rgP[j] = rgT[j] = rgSS[j] = rgDD[j] = 0ull; }

    u64t mse2 = 0ull;
    float ssim_acc = 0.f;
    const bool emit_col = (tid <= 250);

    // Preload rows 0 and 1
    float2 pp0 = ((const float2*)(pbase + (size_t)(y0 + 0) * IMG_W))[tid];
    float2 tt0 = ((const float2*)(tbase + (size_t)(y0 + 0) * IMG_W))[tid];
    float2 pp1 = ((const float2*)(pbase + (size_t)(y0 + 1) * IMG_W))[tid];
    float2 tt1 = ((const float2*)(tbase + (size_t)(y0 + 1) * IMG_W))[tid];

    for (int rb = 0; rb < 44; rb += 22) {          // 22 ≡ 0 (mod 11)
#pragma unroll
        for (int pj = 0; pj < 11; ++pj) {
            const int r0 = rb + 2 * pj;            // even row of pair
            const int j0 = (2 * pj) % 11;          // static slot indices
            const int j1 = (2 * pj + 1) % 11;
            if (r0 < n_in) {                       // block-uniform
                const bool hasem = (r0 >= HALO);   // block-uniform

                // ---- insert row r0 into ring (registers only) ----
                {
                    float s0 = pp0.x + tt0.x, d0 = pp0.x - tt0.x;
                    float s1 = pp0.y + tt0.y, d1 = pp0.y - tt0.y;
                    rgP[j0]  = pk2(pp0.x, pp0.y);
                    rgT[j0]  = pk2(tt0.x, tt0.y);
                    rgSS[j0] = pk2(s0 * s0, s1 * s1);
                    u64t DD  = pk2(d0 * d0, d1 * d1);
                    rgDD[j0] = DD;
                    if (r0 < mse_rows) mse2 = add2(mse2, DD);
                }

                // ---- vertical gather for o0 = r0-10 (BEFORE r1 insert evicts
                //      row r0-10 from the ring) ----
                u64t vb0[4];
                if (hasem) {
#pragma unroll
                    for (int i = 0; i < 11; ++i) {
                        const int sl = (j0 + 1 + i) % 11;   // row o0+i
                        if (i == 0) {
                            vb0[0] = mul2(GWP[0], rgP[sl]);
                            vb0[1] = mul2(GWP[0], rgT[sl]);
                            vb0[2] = mul2(GWP[0], rgSS[sl]);
                            vb0[3] = mul2(GWP[0], rgDD[sl]);
                        } else {
                            vb0[0] = fma2(GWP[i], rgP[sl],  vb0[0]);
                            vb0[1] = fma2(GWP[i], rgT[sl],  vb0[1]);
                            vb0[2] = fma2(GWP[i], rgSS[sl], vb0[2]);
                            vb0[3] = fma2(GWP[i], rgDD[sl], vb0[3]);
                        }
                    }
                }

                // ---- insert row r1 ----
                {
                    float s0 = pp1.x + tt1.x, d0 = pp1.x - tt1.x;
                    float s1 = pp1.y + tt1.y, d1 = pp1.y - tt1.y;
                    rgP[j1]  = pk2(pp1.x, pp1.y);
                    rgT[j1]  = pk2(tt1.x, tt1.y);
                    rgSS[j1] = pk2(s0 * s0, s1 * s1);
                    u64t DD  = pk2(d0 * d0, d1 * d1);
                    rgDD[j1] = DD;
                    if (r0 + 1 < mse_rows) mse2 = add2(mse2, DD);
                }

                // ---- prefetch next pair (hide LDG across hblur phase) ----
                if (r0 + 2 < n_in) {
                    const size_t off = (size_t)(y0 + r0 + 2) * IMG_W;
                    pp0 = ((const float2*)(pbase + off))[tid];
                    tt0 = ((const float2*)(tbase + off))[tid];
                    const size_t off1 = off + IMG_W;
                    pp1 = ((const float2*)(pbase + off1))[tid];
                    tt1 = ((const float2*)(tbase + off1))[tid];
                }

                if (hasem) {
                    // ---- vertical gather for o1 = r1-10 ----
                    u64t vb1[4];
#pragma unroll
                    for (int i = 0; i < 11; ++i) {
                        const int sl = (j1 + 1 + i) % 11;
                        if (i == 0) {
                            vb1[0] = mul2(GWP[0], rgP[sl]);
                            vb1[1] = mul2(GWP[0], rgT[sl]);
                            vb1[2] = mul2(GWP[0], rgSS[sl]);
                            vb1[3] = mul2(GWP[0], rgDD[sl]);
                        } else {
                            vb1[0] = fma2(GWP[i], rgP[sl],  vb1[0]);
                            vb1[1] = fma2(GWP[i], rgT[sl],  vb1[1]);
                            vb1[2] = fma2(GWP[i], rgSS[sl], vb1[2]);
                            vb1[3] = fma2(GWP[i], rgDD[sl], vb1[3]);
                        }
                    }

                    // ---- store both vblurred rows to smem (pair-interleaved) ----
                    const int par = ((r0 - HALO) >> 1) & 1;
                    {
                        float a0, a1, b0, b1;
                        upk2(vb0[0], a0, a1); upk2(vb0[1], b0, b1);
                        sAB[par][0][tid] = make_float4(a0, a1, b0, b1);
                        upk2(vb0[2], a0, a1); upk2(vb0[3], b0, b1);
                        sCD[par][0][tid] = make_float4(a0, a1, b0, b1);
                        upk2(vb1[0], a0, a1); upk2(vb1[1], b0, b1);
                        sAB[par][1][tid] = make_float4(a0, a1, b0, b1);
                        upk2(vb1[2], a0, a1); upk2(vb1[3], b0, b1);
                        sCD[par][1][tid] = make_float4(a0, a1, b0, b1);
                    }

                    // ---- NEIGHBOR rendezvous instead of block barrier ----
                    // hblur of warp w reads only warp w and w+1's stores, so a
                    // pairwise (w,w+1) sync suffices. Named barriers ids 1..7,
                    // count 64, right-neighbor first (linear chain, no cycle:
                    // warp 7 resolves first, then 6, ...). Warps may slide one
                    // phase per hop -> no block-wide convoy alignment.
                    if (warp < 7) named_bar(1 + warp);       // with right nbr
                    if (warp > 0) named_bar(warp);           // with left  nbr

                    // ---- horizontal blur + SSIM for both completed rows ----
#pragma unroll
                    for (int rr = 0; rr < 2; ++rr) {
                        u64t M1p, M2p, BSp, BDp;
                        hblur2(sAB[par][rr], tid, GWP, M1p, M2p);
                        hblur2(sCD[par][rr], tid, GWP, BSp, BDp);
                        if (emit_col) {
                            float M1[2], M2[2], BS[2], BD[2];
                            upk2(M1p, M1[0], M1[1]);
                            upk2(M2p, M2[0], M2[1]);
                            upk2(BSp, BS[0], BS[1]);
                            upk2(BDp, BD[0], BD[1]);
#pragma unroll
                            for (int col = 0; col < 2; ++col) {
                                float m1s = M1[col] * M1[col];
                                float m2s = M2[col] * M2[col];
                                float m12 = M1[col] * M2[col];
                                float sums = m1s + m2s;
                                float sigsum = fmaf(0.5f,  BS[col] + BD[col], -sums);
                                float sig12  = fmaf(0.25f, BS[col] - BD[col], -m12);
                                float num = (2.f * m12 + C1) * (2.f * sig12 + C2);
                                float den = fmaf(sums + C1, sigsum + C2, 1e-6f);
                                ssim_acc += __fdividef(num, den);
                            }
                        }
                    }
                }
            }
        }
    }

    // Unpack packed MSE accumulator
    float mse_acc;
    { float mlo, mhi; upk2(mse2, mlo, mhi); mse_acc = mlo + mhi; }

    // Block reduction (full __syncthreads resynchronizes the skewed warps)
#pragma unroll
    for (int off = 16; off > 0; off >>= 1) {
        mse_acc  += __shfl_down_sync(0xffffffffu, mse_acc,  off);
        ssim_acc += __shfl_down_sync(0xffffffffu, ssim_acc, off);
    }
    const int lane = tid & 31;
    if (lane == 0) { red_m[warp] = mse_acc; red_s[warp] = ssim_acc; }
    __syncthreads();
    if (tid == 0) {
        float m = 0.f, s = 0.f;
#pragma unroll
        for (int w = 0; w < 8; ++w) { m += red_m[w]; s += red_s[w]; }
        const int bid = blockIdx.y * NSTRIPS + blockIdx.x;
        g_partial[bid * 2 + 0] = m;
        g_partial[bid * 2 + 1] = s;
        __threadfence();
        s_ticket = atomicAdd(&g_count, 1u);
    }
    __syncthreads();

    // Last block folds in the final reduction (no 2nd launch)
    if (s_ticket == NBLOCKS - 1) {
        __threadfence();
        double m = 0.0, s = 0.0;
        for (int i = tid; i < NBLOCKS; i += NTHREADS) {
            m += (double)g_partial[i * 2 + 0];
            s += (double)g_partial[i * 2 + 1];
        }
#pragma unroll
        for (int off = 16; off > 0; off >>= 1) {
            m += __shfl_down_sync(0xffffffffu, m, off);
            s += __shfl_down_sync(0xffffffffu, s, off);
        }
        __shared__ double sm[8], ss[8];
        if (lane == 0) { sm[warp] = m; ss[warp] = s; }
        __syncthreads();
        if (tid == 0) {
            double M = 0.0, S = 0.0;
#pragma unroll
            for (int w = 0; w < 8; ++w) { M += sm[w]; S += ss[w]; }
            const double mse_n  = (double)NIMG * IMG_H * IMG_W;
            const double ssim_n = (double)NIMG * OUT_H * OUT_W;
            double mse_loss  = M / mse_n;
            double ssim_loss = 1.0 - S / ssim_n;
            out[0] = (float)(0.6 * mse_loss + 0.4 * ssim_loss);
            g_count = 0;   // self-reset for next graph replay
        }
    }
}

extern "C" void kernel_launch(void* const* d_in, const int* in_sizes, int n_in,
                              void* d_out, int out_size)
{
    const float* pred = (const float*)d_in[0];
    const float* targ = (const float*)d_in[1];

    dim3 grid(NSTRIPS, NIMG, 1);   // 18 x 32 = 576 blocks
    fused_mse_ssim<<<grid, NTHREADS>>>(pred, targ, (float*)d_out);
}

// round 15
// speedup vs baseline: 1.0313x; 1.0284x over previous
#include <cuda_runtime.h>

#define IMG_H 512
#define IMG_W 512
#define OUT_H 502
#define OUT_W 502
#define NIMG 32
#define HALO 10
#define STRIP 28          // output rows per block (18 strips: 17x28 + 26)
#define NSTRIPS 18
#define NTHREADS 256
#define NBLOCKS (NSTRIPS * NIMG)   // 576 = 97.3% of 2 full waves at occ 2
#define NCP 266           // column-pairs per smem row (264 used + pad)

__device__ float g_partial[NBLOCKS * 2];
__device__ unsigned g_count = 0;

// ---- packed f32x2 helpers (ptxas never fuses these from C++) ----
typedef unsigned long long u64t;
__device__ __forceinline__ u64t pk2(float lo, float hi) {
    u64t r; asm("mov.b64 %0, {%1,%2};" : "=l"(r) : "f"(lo), "f"(hi)); return r;
}
__device__ __forceinline__ void upk2(u64t v, float& lo, float& hi) {
    asm("mov.b64 {%0,%1}, %2;" : "=f"(lo), "=f"(hi) : "l"(v));
}
__device__ __forceinline__ u64t fma2(u64t a, u64t b, u64t c) {
    u64t d; asm("fma.rn.f32x2 %0, %1, %2, %3;" : "=l"(d) : "l"(a), "l"(b), "l"(c)); return d;
}
__device__ __forceinline__ u64t mul2(u64t a, u64t b) {
    u64t d; asm("mul.rn.f32x2 %0, %1, %2;" : "=l"(d) : "l"(a), "l"(b)); return d;
}
__device__ __forceinline__ u64t add2(u64t a, u64t b) {
    u64t d; asm("add.rn.f32x2 %0, %1, %2;" : "=l"(d) : "l"(a), "l"(b)); return d;
}

// Horizontal 11-tap blur for 2 adjacent output cols, TWO channels at once.
// Pair-interleave (A_even, A_odd, B_even, B_odd): even-k packs are adjacent
// register pairs from LDS.128 (fold free); only 5 odd-k packs/channel are real.
__device__ __forceinline__ void hblur2(const float4* __restrict__ row, int tid,
                                       const u64t* __restrict__ GWP,
                                       u64t& hA, u64t& hB)
{
    float4 q[6];
#pragma unroll
    for (int m = 0; m < 6; ++m) q[m] = row[tid + m];
    hA = mul2(GWP[0], pk2(q[0].x, q[0].y));
    hB = mul2(GWP[0], pk2(q[0].z, q[0].w));
#pragma unroll
    for (int k = 1; k < 11; ++k) {
        const int m = k >> 1;
        u64t PA = (k & 1) ? pk2(q[m].y, q[m + 1].x) : pk2(q[m].x, q[m].y);
        u64t PB = (k & 1) ? pk2(q[m].w, q[m + 1].z) : pk2(q[m].z, q[m].w);
        hA = fma2(GWP[k], PA, hA);
        hB = fma2(GWP[k], PB, hB);
    }
}

// hblur + SSIM accumulation for the 2 rows of one parity buffer.
__device__ __forceinline__ void hblur_ssim_phase(
    const float4 (*__restrict__ bAB)[NCP], const float4 (*__restrict__ bCD)[NCP],
    int tid, const u64t* __restrict__ GWP, bool emit_col,
    float C1, float C2, float& ssim_acc)
{
#pragma unroll
    for (int rr = 0; rr < 2; ++rr) {
        u64t M1p, M2p, BSp, BDp;
        hblur2(bAB[rr], tid, GWP, M1p, M2p);
        hblur2(bCD[rr], tid, GWP, BSp, BDp);
        if (emit_col) {
            float M1[2], M2[2], BS[2], BD[2];
            upk2(M1p, M1[0], M1[1]);
            upk2(M2p, M2[0], M2[1]);
            upk2(BSp, BS[0], BS[1]);
            upk2(BDp, BD[0], BD[1]);
#pragma unroll
            for (int col = 0; col < 2; ++col) {
                float m1s = M1[col] * M1[col];
                float m2s = M2[col] * M2[col];
                float m12 = M1[col] * M2[col];
                float sums = m1s + m2s;
                float sigsum = fmaf(0.5f,  BS[col] + BD[col], -sums);
                float sig12  = fmaf(0.25f, BS[col] - BD[col], -m12);
                float num = (2.f * m12 + C1) * (2.f * sig12 + C2);
                float den = fmaf(sums + C1, sigsum + C2, 1e-6f);
                ssim_acc += __fdividef(num, den);
            }
        }
    }
}

__global__ __launch_bounds__(NTHREADS, 2)
void fused_mse_ssim(const float* __restrict__ pred, const float* __restrict__ targ,
                    float* __restrict__ out)
{
    const float GW[11] = {
        0.00102838f, 0.00759876f, 0.03600077f, 0.10936070f, 0.21300554f,
        0.26601172f,
        0.21300554f, 0.10936070f, 0.03600077f, 0.00759876f, 0.00102838f
    };
    u64t GWP[11];
#pragma unroll
    for (int k = 0; k < 11; ++k) GWP[k] = pk2(GW[k], GW[k]);
    const float C1 = 1e-4f, C2 = 9e-4f;

    // Smem holds VERTICALLY-BLURRED completed rows (2 rows/phase, 2 parities).
    __shared__ float4 sAB[2][2][NCP];   // (VP0, VP1, VT0, VT1)
    __shared__ float4 sCD[2][2][NCP];   // (VSS0, VSS1, VDD0, VDD1)
    __shared__ float red_m[8], red_s[8];
    __shared__ unsigned s_ticket;

    const int tid  = threadIdx.x;
    const int warp = tid >> 5;
    const int y0  = blockIdx.x * STRIP;
    const int img = blockIdx.y;

    const int n_in     = min(STRIP, OUT_H - y0) + HALO;   // 38 or 36 (even)
    const int mse_rows = min(IMG_H - y0, (blockIdx.x == NSTRIPS - 1) ? 999 : STRIP);

    const float* __restrict__ pbase = pred + (size_t)img * (IMG_H * IMG_W);
    const float* __restrict__ tbase = targ + (size_t)img * (IMG_H * IMG_W);

    // Ring of RAW channel values (col-pair packed): 11 rows x 4 channels.
    u64t rgP[11], rgT[11], rgSS[11], rgDD[11];
#pragma unroll
    for (int j = 0; j < 11; ++j) { rgP[j] = rgT[j] = rgSS[j] = rgDD[j] = 0ull; }

    u64t mse2 = 0ull;
    float ssim_acc = 0.f;
    const bool emit_col = (tid <= 250);

    // Preload rows 0 and 1
    float2 pp0 = ((const float2*)(pbase + (size_t)(y0 + 0) * IMG_W))[tid];
    float2 tt0 = ((const float2*)(tbase + (size_t)(y0 + 0) * IMG_W))[tid];
    float2 pp1 = ((const float2*)(pbase + (size_t)(y0 + 1) * IMG_W))[tid];
    float2 tt1 = ((const float2*)(tbase + (size_t)(y0 + 1) * IMG_W))[tid];

    // SOFTWARE PIPELINE: phase p stores its vblurred rows to par(p)=((r0-10)/2)&1,
    // and runs hblur+SSIM for phase p-1 (par^1) in the SAME straight-line region
    // so ptxas interleaves prev-phase LDS/hblur with cur-phase vgather chains.
    // One __syncthreads per phase separates cur stores (pre-bar) from next
    // phase's reads (post-bar), and prev reads (pre-bar) from the par^1
    // overwrite in phase p+1 (post-bar). Final phase handled in epilogue.
    for (int rb = 0; rb < 44; rb += 22) {          // 22 ≡ 0 (mod 11)
#pragma unroll
        for (int pj = 0; pj < 11; ++pj) {
            const int r0 = rb + 2 * pj;            // even row of pair
            const int j0 = (2 * pj) % 11;          // static slot indices
            const int j1 = (2 * pj + 1) % 11;
            if (r0 < n_in) {                       // block-uniform
                const bool hasem = (r0 >= HALO);       // STATIC per iteration
                const bool hasprev = (r0 >= HALO + 2); // STATIC per iteration
                const int par = ((r0 - HALO) >> 1) & 1;

                // ---- insert row r0 into ring (registers only) ----
                {
                    float s0 = pp0.x + tt0.x, d0 = pp0.x - tt0.x;
                    float s1 = pp0.y + tt0.y, d1 = pp0.y - tt0.y;
                    rgP[j0]  = pk2(pp0.x, pp0.y);
                    rgT[j0]  = pk2(tt0.x, tt0.y);
                    rgSS[j0] = pk2(s0 * s0, s1 * s1);
                    u64t DD  = pk2(d0 * d0, d1 * d1);
                    rgDD[j0] = DD;
                    if (r0 < mse_rows) mse2 = add2(mse2, DD);
                }

                // ---- vertical gather for o0 = r0-10 (BEFORE r1 insert evicts
                //      row r0-10 from the ring), store immediately ----
                if (hasem) {
                    u64t v0, v1, v2, v3;
#pragma unroll
                    for (int i = 0; i < 11; ++i) {
                        const int sl = (j0 + 1 + i) % 11;
                        if (i == 0) {
                            v0 = mul2(GWP[0], rgP[sl]);
                            v1 = mul2(GWP[0], rgT[sl]);
                            v2 = mul2(GWP[0], rgSS[sl]);
                            v3 = mul2(GWP[0], rgDD[sl]);
                        } else {
                            v0 = fma2(GWP[i], rgP[sl],  v0);
                            v1 = fma2(GWP[i], rgT[sl],  v1);
                            v2 = fma2(GWP[i], rgSS[sl], v2);
                            v3 = fma2(GWP[i], rgDD[sl], v3);
                        }
                    }
                    float a0, a1, b0, b1;
                    upk2(v0, a0, a1); upk2(v1, b0, b1);
                    sAB[par][0][tid] = make_float4(a0, a1, b0, b1);
                    upk2(v2, a0, a1); upk2(v3, b0, b1);
                    sCD[par][0][tid] = make_float4(a0, a1, b0, b1);
                }

                // ---- insert row r1 ----
                {
                    float s0 = pp1.x + tt1.x, d0 = pp1.x - tt1.x;
                    float s1 = pp1.y + tt1.y, d1 = pp1.y - tt1.y;
                    rgP[j1]  = pk2(pp1.x, pp1.y);
                    rgT[j1]  = pk2(tt1.x, tt1.y);
                    rgSS[j1] = pk2(s0 * s0, s1 * s1);
                    u64t DD  = pk2(d0 * d0, d1 * d1);
                    rgDD[j1] = DD;
                    if (r0 + 1 < mse_rows) mse2 = add2(mse2, DD);
                }

                // ---- vertical gather for o1 = r1-10, store ----
                if (hasem) {
                    u64t v0, v1, v2, v3;
#pragma unroll
                    for (int i = 0; i < 11; ++i) {
                        const int sl = (j1 + 1 + i) % 11;
                        if (i == 0) {
                            v0 = mul2(GWP[0], rgP[sl]);
                            v1 = mul2(GWP[0], rgT[sl]);
                            v2 = mul2(GWP[0], rgSS[sl]);
                            v3 = mul2(GWP[0], rgDD[sl]);
                        } else {
                            v0 = fma2(GWP[i], rgP[sl],  v0);
                            v1 = fma2(GWP[i], rgT[sl],  v1);
                            v2 = fma2(GWP[i], rgSS[sl], v2);
                            v3 = fma2(GWP[i], rgDD[sl], v3);
                        }
                    }
                    float a0, a1, b0, b1;
                    upk2(v0, a0, a1); upk2(v1, b0, b1);
                    sAB[par][1][tid] = make_float4(a0, a1, b0, b1);
                    upk2(v2, a0, a1); upk2(v3, b0, b1);
                    sCD[par][1][tid] = make_float4(a0, a1, b0, b1);
                }

                // ---- prefetch next pair ----
                if (r0 + 2 < n_in) {
                    const size_t off = (size_t)(y0 + r0 + 2) * IMG_W;
                    pp0 = ((const float2*)(pbase + off))[tid];
                    tt0 = ((const float2*)(tbase + off))[tid];
                    const size_t off1 = off + IMG_W;
                    pp1 = ((const float2*)(pbase + off1))[tid];
                    tt1 = ((const float2*)(tbase + off1))[tid];
                }

                // ---- PIPELINED: hblur + SSIM for PREVIOUS phase (par^1).
                //      Data synced by prev barrier; its parity is rewritten
                //      only in phase p+1 after the barrier below. ptxas
                //      interleaves these LDS/FMAs with the vgather above. ----
                if (hasprev)
                    hblur_ssim_phase(sAB[par ^ 1], sCD[par ^ 1], tid, GWP,
                                     emit_col, C1, C2, ssim_acc);

                __syncthreads();
            }
        }
    }

    // ---- epilogue: hblur + SSIM for the final phase (runtime parity) ----
    {
        const int par_last = ((n_in - 2 - HALO) >> 1) & 1;
        hblur_ssim_phase(sAB[par_last], sCD[par_last], tid, GWP,
                         emit_col, C1, C2, ssim_acc);
    }

    // Unpack packed MSE accumulator
    float mse_acc;
    { float mlo, mhi; upk2(mse2, mlo, mhi); mse_acc = mlo + mhi; }

    // Block reduction
#pragma unroll
    for (int off = 16; off > 0; off >>= 1) {
        mse_acc  += __shfl_down_sync(0xffffffffu, mse_acc,  off);
        ssim_acc += __shfl_down_sync(0xffffffffu, ssim_acc, off);
    }
    const int lane = tid & 31;
    if (lane == 0) { red_m[warp] = mse_acc; red_s[warp] = ssim_acc; }
    __syncthreads();
    if (tid == 0) {
        float m = 0.f, s = 0.f;
#pragma unroll
        for (int w = 0; w < 8; ++w) { m += red_m[w]; s += red_s[w]; }
        const int bid = blockIdx.y * NSTRIPS + blockIdx.x;
        g_partial[bid * 2 + 0] = m;
        g_partial[bid * 2 + 1] = s;
        __threadfence();
        s_ticket = atomicAdd(&g_count, 1u);
    }
    __syncthreads();

    // Last block folds in the final reduction (no 2nd launch)
    if (s_ticket == NBLOCKS - 1) {
        __threadfence();
        double m = 0.0, s = 0.0;
        for (int i = tid; i < NBLOCKS; i += NTHREADS) {
            m += (double)g_partial[i * 2 + 0];
            s += (double)g_partial[i * 2 + 1];
        }
#pragma unroll
        for (int off = 16; off > 0; off >>= 1) {
            m += __shfl_down_sync(0xffffffffu, m, off);
            s += __shfl_down_sync(0xffffffffu, s, off);
        }
        __shared__ double sm[8], ss[8];
        if (lane == 0) { sm[warp] = m; ss[warp] = s; }
        __syncthreads();
        if (tid == 0) {
            double M = 0.0, S = 0.0;
#pragma unroll
            for (int w = 0; w < 8; ++w) { M += sm[w]; S += ss[w]; }
            const double mse_n  = (double)NIMG * IMG_H * IMG_W;
            const double ssim_n = (double)NIMG * OUT_H * OUT_W;
            double mse_loss  = M / mse_n;
            double ssim_loss = 1.0 - S / ssim_n;
            out[0] = (float)(0.6 * mse_loss + 0.4 * ssim_loss);
            g_count = 0;   // self-reset for next graph replay
        }
    }
}

extern "C" void kernel_launch(void* const* d_in, const int* in_sizes, int n_in,
                              void* d_out, int out_size)
{
    const float* pred = (const float*)d_in[0];
    const float* targ = (const float*)d_in[1];

    dim3 grid(NSTRIPS, NIMG, 1);   // 18 x 32 = 576 blocks
    fused_mse_ssim<<<grid, NTHREADS>>>(pred, targ, (float*)d_out);
}